// round 3
// baseline (speedup 1.0000x reference)
#include <cuda_runtime.h>
#include <math.h>

#define NT        1024
#define NFRAMES   6000
#define NTEMPI    60
#define NBEATS    4
#define NTRANS    (NBEATS * NTEMPI)     // 240
#define LT_STRIDE 61
#define LT2SZ     (NBEATS * NTEMPI * LT_STRIDE)   // 14640
#define CH        20                    // states per bulk thread
#define NBULK     768                   // threads 256..1023
#define SPAD      (NBULK * CH)          // 15360 padded state count
#define FIXCAP    1536

// -------- smem layout (floats) --------
// [0 .. SPAD+3]                vA physical (vA = sm+4, states 0..SPAD-1)
// [SPAD+4 .. 2*SPAD+7]         vB physical (vB = sm+SPAD+8)
#define OFF_LT2   (2 * SPAD + 8)
#define OFF_CAND  (OFF_LT2 + LT2SZ)
#define OFF_PREV  (OFF_CAND + 256)
#define OFF_FIX   (OFF_PREV + 256)
#define OFF_NFIX  (OFF_FIX + FIXCAP)
#define OFF_RV    (OFF_NFIX + 4)
#define OFF_RI    (OFF_RV + NT)
#define SMEM_FLOATS (OFF_RI + NT)
#define SMEM_BYTES  (SMEM_FLOATS * 4)

__device__ float g_dens[NFRAMES * 3];
__device__ int   g_bp[NFRAMES * NTRANS];

__global__ void dens_kernel(const float* __restrict__ acts) {
    int t = blockIdx.x * blockDim.x + threadIdx.x;
    if (t < NFRAMES) {
        float ab = acts[2 * t];
        float ad = acts[2 * t + 1];
        g_dens[3 * t + 0] = logf((1.0f - ab - ad) / 15.0f);
        g_dens[3 * t + 1] = logf(ab);
        g_dens[3 * t + 2] = logf(ad);
    }
}

__global__ __launch_bounds__(NT, 1)
void viterbi_kernel(const float* __restrict__ log_trans,
                    const int*   __restrict__ prev_last,
                    const int*   __restrict__ first_states,
                    const int*   __restrict__ pointer,
                    float*       __restrict__ out,
                    int S, int out_size)
{
    extern __shared__ float sm[];
    float* vA    = sm + 4;
    float* vB    = sm + SPAD + 8;
    float* lt2   = sm + OFF_LT2;                 // [b][i][j], stride 61
    float* sCand = sm + OFF_CAND;
    int*   sPrev = (int*)(sm + OFF_PREV);
    int*   fixL  = (int*)(sm + OFF_FIX);
    int*   nFixP = (int*)(sm + OFF_NFIX);
    float* rv    = sm + OFF_RV;
    int*   ri    = (int*)(sm + OFF_RI);

    const int tid = threadIdx.x;

    // ================= init =================
    if (tid == 0) *nFixP = 0;
    float v0 = -logf((float)S);
    for (int s = tid; s < SPAD; s += NT) vA[s] = v0;

    // lt2: transposed-to-row layout with pad-61 (conflict-free scalar LDS)
    for (int idx = tid; idx < NBEATS * NTEMPI * NTEMPI; idx += NT) {
        int b = idx / (NTEMPI * NTEMPI);
        int r = (idx - b * NTEMPI * NTEMPI) / NTEMPI;
        int c = idx % NTEMPI;
        lt2[b * NTEMPI * LT_STRIDE + r * LT_STRIDE + c] = log_trans[idx];
    }
    if (tid < NTRANS) sPrev[tid] = prev_last[tid];

    // mark first states using vB as int scratch (vB rewritten at t=0 anyway)
    int* mark = (int*)vB;
    for (int s = tid; s < SPAD; s += NT) mark[s] = 0;
    __syncthreads();
    int firstS = 0;
    if (tid < NTRANS) {
        firstS = first_states[tid];
        mark[firstS] = 1;
    }
    __syncthreads();
    // fix list: non-first states with ptr != 0
    for (int s = tid; s < S; s += NT) {
        int p = pointer[s];
        if (p != 0 && mark[s] == 0) {
            int idx = atomicAdd(nFixP, 1);
            if (idx < FIXCAP) fixL[idx] = s | ((p - 1) << 14);
        }
    }
    __syncthreads();
    const int nFix = *nFixP;

    // A-thread statics: beat/tempo split, finite-transition window
    int b60 = 0, i60 = 0, lo = 0, hi = 0;
    float dFirstIs2 = 0.0f;
    if (tid < NTRANS) {
        b60 = tid / NTEMPI;
        i60 = tid - b60 * NTEMPI;
        dFirstIs2 = (b60 == 0) ? 1.0f : 0.0f;
        const float* row = lt2 + b60 * NTEMPI * LT_STRIDE + i60 * LT_STRIDE;
        lo = NTEMPI; hi = -1;
        for (int j = 0; j < NTEMPI; j++) {
            if (row[j] > -1e29f) { if (j < lo) lo = j; hi = j; }
        }
    }
    __syncthreads();

    const int u  = tid - 256;          // bulk thread index
    const int s0 = u * CH;

    float* vO = vA;
    float* vN = vB;

    // ================= 6000 Viterbi steps =================
    for (int t = 0; t < NFRAMES; t++) {
        float d0 = g_dens[3 * t + 0];
        float d1 = g_dens[3 * t + 1];
        float d2 = g_dens[3 * t + 2];

        __syncthreads();   // sync1: vO fully valid (prev fix done)

        float bestReg = 0.0f;
        if (tid < 256) {
            // ---- Phase A: 240 threads, concurrent with bulk ----
            if (tid < NTRANS) sCand[tid] = vO[sPrev[tid]];
            asm volatile("bar.sync 1, 256;" ::: "memory");
            if (tid < NTRANS) {
                const float* c   = sCand + b60 * NTEMPI;
                const float* row = lt2 + b60 * NTEMPI * LT_STRIDE + i60 * LT_STRIDE;
                float best = -3.0e38f;
                int   arg  = lo;
                for (int j = lo; j <= hi; j++) {
                    float sc = c[j] + row[j];
                    if (sc > best) { best = sc; arg = j; }
                }
                g_bp[t * NTRANS + tid] = sPrev[b60 * NTEMPI + arg];
                bestReg = best;
            }
        } else {
            // ---- Phase B bulk: vN[s] = vO[s-1] + d0, vectorized ----
            const float4* src = (const float4*)(vO + s0 - 4);
            float4*       dst = (float4*)(vN + s0);
            float carry = src[0].w;
            #pragma unroll
            for (int j = 1; j <= CH / 4; j++) {
                float4 L = src[j];
                float4 o;
                o.x = carry + d0;
                o.y = L.x + d0;
                o.z = L.y + d0;
                o.w = L.z + d0;
                dst[j - 1] = o;
                carry = L.w;
            }
        }

        __syncthreads();   // sync2: bulk writes done

        // ---- fix pass: overwrite ptr!=0 states and first states ----
        if (tid < NTRANS) {
            vN[firstS] = bestReg + (dFirstIs2 != 0.0f ? d2 : d1);
        }
        for (int e = tid; e < nFix; e += NT) {
            int c = fixL[e];
            int s = c & 0x3FFF;
            vN[s] = vO[s - 1] + ((c >> 14) ? d2 : d1);
        }

        float* tmp = vO; vO = vN; vN = tmp;
    }
    __syncthreads();
    const float* vF = vO;   // after swap, vO holds the final v

    // ================= argmax(v_final), first-index tie-break =================
    float bv = -3.0e38f;
    int   bi = 0x7FFFFFFF;
    for (int s = tid; s < S; s += NT) {
        float x = vF[s];
        if (x > bv) { bv = x; bi = s; }
    }
    rv[tid] = bv; ri[tid] = bi;
    __syncthreads();
    for (int off = NT / 2; off > 0; off >>= 1) {
        if (tid < off) {
            float xv = rv[tid + off]; int xi = ri[tid + off];
            if (xv > rv[tid] || (xv == rv[tid] && xi < ri[tid])) { rv[tid] = xv; ri[tid] = xi; }
        }
        __syncthreads();
    }

    // ================= backtrace =================
    // sFidx overlays lt2 (no longer needed)
    short* sFidx = (short*)lt2;
    for (int s = tid; s < SPAD; s += NT) sFidx[s] = -1;
    __syncthreads();
    if (tid < NTRANS) sFidx[firstS] = (short)tid;
    __syncthreads();

    if (tid == 0) {
        int s = ri[0];
        if (out_size > NFRAMES) out[NFRAMES] = rv[0];
        out[NFRAMES - 1] = (float)s;
        for (int t = NFRAMES - 1; t >= 1; t--) {
            short f = sFidx[s];
            int p = (f >= 0) ? g_bp[t * NTRANS + f] : (s - 1);
            out[t - 1] = (float)p;
            s = p;
        }
    }
}

extern "C" void kernel_launch(void* const* d_in, const int* in_sizes, int n_in,
                              void* d_out, int out_size) {
    const float* acts         = (const float*)d_in[0];
    const float* log_trans    = (const float*)d_in[1];
    const int*   prev_last    = (const int*)d_in[2];
    const int*   first_states = (const int*)d_in[3];
    const int*   pointer      = (const int*)d_in[4];
    int S = in_sizes[4];

    cudaFuncSetAttribute(viterbi_kernel, cudaFuncAttributeMaxDynamicSharedMemorySize, SMEM_BYTES);

    dens_kernel<<<(NFRAMES + 255) / 256, 256>>>(acts);
    viterbi_kernel<<<1, NT, SMEM_BYTES>>>(log_trans, prev_last, first_states, pointer,
                                          (float*)d_out, S, out_size);
}

// round 4
// speedup vs baseline: 1.1991x; 1.1991x over previous
#include <cuda_runtime.h>
#include <math.h>

#define NT        512
#define NFRAMES   6000
#define NTEMPI    60
#define NBEATS    4
#define NTRANS    (NBEATS * NTEMPI)     // 240
#define LT_STRIDE 61
#define LT2SZ     (NBEATS * NTEMPI * LT_STRIDE)   // 14640
#define SPAD      15360
#define FIXCAP    1024
#define MAXFIX    4                      // per fix thread (256 fix threads)

// -------- smem layout (floats) --------
#define OFF_VV    0
#define OFF_W     (OFF_VV + SPAD)
#define OFF_LT2   (OFF_W + SPAD)
#define OFF_CAND  (OFF_LT2 + LT2SZ)
#define OFF_PREV  (OFF_CAND + 256)
#define OFF_BASE  (OFF_PREV + 256)
#define OFF_LEN   (OFF_BASE + 256)
#define OFF_FIX   (OFF_LEN + 256)
#define OFF_NFIX  (OFF_FIX + FIXCAP)
#define OFF_RV    (OFF_NFIX + 4)
#define OFF_RI    (OFF_RV + NT)
#define OFF_SUM   (OFF_RI + NT)
#define OFF_IVL   (OFF_SUM + 4)          // ushort[SPAD] = SPAD/2 floats
#define SMEM_FLOATS (OFF_IVL + SPAD / 2)
#define SMEM_BYTES  (SMEM_FLOATS * 4)

__device__ float4 g_c4[NFRAMES];         // {d1-d0, d2-d0, d0, 0}
__device__ int    g_bp[NFRAMES * NTRANS];

__global__ void dens_kernel(const float* __restrict__ acts) {
    int t = blockIdx.x * blockDim.x + threadIdx.x;
    if (t < NFRAMES) {
        float ab = acts[2 * t];
        float ad = acts[2 * t + 1];
        float d0 = logf((1.0f - ab - ad) / 15.0f);
        float d1 = logf(ab);
        float d2 = logf(ad);
        g_c4[t] = make_float4(d1 - d0, d2 - d0, d0, 0.0f);
    }
}

__global__ __launch_bounds__(NT, 1)
void viterbi_kernel(const float* __restrict__ log_trans,
                    const int*   __restrict__ prev_last,
                    const int*   __restrict__ first_states,
                    const int*   __restrict__ pointer,
                    float*       __restrict__ out,
                    int S, int out_size)
{
    extern __shared__ float sm[];
    float*           vv    = sm + OFF_VV;
    float*           wArr  = sm + OFF_W;
    float*           lt2   = sm + OFF_LT2;
    float*           sCand = sm + OFF_CAND;
    int*             sPrev = (int*)(sm + OFF_PREV);
    int*             sBase = (int*)(sm + OFF_BASE);
    int*             sLen  = (int*)(sm + OFF_LEN);
    int*             fixL  = (int*)(sm + OFF_FIX);
    int*             nFixP = (int*)(sm + OFF_NFIX);
    float*           rv    = sm + OFF_RV;
    int*             ri    = (int*)(sm + OFF_RI);
    float*           sSum  = sm + OFF_SUM;
    unsigned short*  sIvl  = (unsigned short*)(sm + OFF_IVL);

    const int tid = threadIdx.x;
    const int nsb = S / NBEATS;

    // ================= init =================
    if (tid == 0) *nFixP = 0;
    float v0 = -logf((float)S);
    for (int s = tid; s < SPAD; s += NT) vv[s] = v0;

    for (int idx = tid; idx < NBEATS * NTEMPI * NTEMPI; idx += NT) {
        int b = idx / (NTEMPI * NTEMPI);
        int r = (idx - b * NTEMPI * NTEMPI) / NTEMPI;
        int c = idx % NTEMPI;
        lt2[b * NTEMPI * LT_STRIDE + r * LT_STRIDE + c] = log_trans[idx];
    }
    if (tid < NTRANS) {
        sPrev[tid] = prev_last[tid];
        sBase[tid] = first_states[tid];
    }
    __syncthreads();

    int b60 = 0, i60 = 0, myBase = 0, myL = 1, srcBase = 0, lo = 0, hi = 0;
    if (tid < NTRANS) {
        b60 = tid / NTEMPI;
        i60 = tid - b60 * NTEMPI;
        myBase = sBase[tid];
        int end = (i60 < NTEMPI - 1) ? sBase[tid + 1] : (b60 + 1) * nsb;
        myL = end - myBase;
        srcBase = (b60 == 0) ? (myBase + 3 * nsb) : (myBase - nsb);
        // finite-transition window
        const float* row = lt2 + b60 * NTEMPI * LT_STRIDE + i60 * LT_STRIDE;
        lo = NTEMPI; hi = -1;
        for (int j = 0; j < NTEMPI; j++)
            if (row[j] > -1e29f) { if (j < lo) lo = j; hi = j; }
    }
    __syncthreads();
    if (tid < NTRANS) {
        sLen[tid] = myL;
        for (int o = 0; o < myL; o++) sIvl[myBase + o] = (unsigned short)tid;
    }
    __syncthreads();

    // fix list: non-first states with ptr != 0
    for (int s = tid; s < S; s += NT) {
        int p = pointer[s];
        if (p != 0) {
            int iv = sIvl[s];
            if (s != sBase[iv]) {
                int idx = atomicAdd(nFixP, 1);
                if (idx < FIXCAP) fixL[idx] = s | ((p - 1) << 14);
            }
        }
    }
    __syncthreads();
    int nFix = *nFixP; if (nFix > FIXCAP) nFix = FIXCAP;

    // fix-thread setup (threads 256..511)
    int fOff[MAXFIX], fBase[MAXFIX], fL[MAXFIX], fC2[MAXFIX], fCnt = 0;
    if (tid >= 256) {
        int u = tid - 256;
        #pragma unroll
        for (int e = 0; e < MAXFIX; e++) {
            int idx = u + e * 256;
            if (idx < nFix) {
                int c = fixL[idx];
                int s = c & 0x3FFF;
                int iv = sIvl[s];
                fBase[e] = sBase[iv];
                fL[e]    = sLen[iv];
                fOff[e]  = (s - fBase[e]) - 1;   // q(o,0) offset = o-1, o>=1
                fC2[e]   = (c >> 14);
                fCnt = e + 1;
            }
        }
    }
    __syncthreads();

    int k = myL - 1;                 // rotating offset (L-1-t) mod L
    const int mid = lo + ((hi - lo + 1) >> 1);
    float4 cc = g_c4[0];
    float sumD0 = 0.0f;

    // ================= 6000 Viterbi steps =================
    for (int t = 0; t < NFRAMES; t++) {
        __syncthreads();             // prev frame's writes visible

        float4 ccn = (t + 1 < NFRAMES) ? g_c4[t + 1] : make_float4(0, 0, 0, 0);

        if (tid < 256) {
            // ---- Phase A ----
            if (tid < NTRANS) sCand[tid] = vv[srcBase + k];
            asm volatile("bar.sync 1, 256;" ::: "memory");
            if (tid < NTRANS) {
                const float* c   = sCand + b60 * NTEMPI;
                const float* row = lt2 + b60 * NTEMPI * LT_STRIDE + i60 * LT_STRIDE;
                float b1 = -3.0e38f; int a1 = lo;
                for (int j = lo; j < mid; j++) {
                    float sc = c[j] + row[j];
                    if (sc > b1) { b1 = sc; a1 = j; }
                }
                float b2 = -3.0e38f; int a2 = mid;
                for (int j = mid; j <= hi; j++) {
                    float sc = c[j] + row[j];
                    if (sc > b2) { b2 = sc; a2 = j; }
                }
                float best; int arg;
                if (b2 > b1) { best = b2; arg = a2; } else { best = b1; arg = a1; }
                float cAdd = (b60 == 0) ? cc.y : cc.x;
                vv[myBase + k] = best + cAdd;
                g_bp[t * NTRANS + tid] = sPrev[b60 * NTEMPI + arg];
                k = (k == 0) ? (myL - 1) : (k - 1);
            }
        } else {
            // ---- fixes (disjoint slots, concurrent with A) ----
            #pragma unroll
            for (int e = 0; e < MAXFIX; e++) {
                if (e < fCnt) {
                    int sl = fBase[e] + fOff[e];
                    vv[sl] += fC2[e] ? cc.y : cc.x;
                    fOff[e] = (fOff[e] == 0) ? (fL[e] - 1) : (fOff[e] - 1);
                }
            }
            if (tid == NT - 1) sumD0 += cc.z;
        }
        cc = ccn;
    }
    __syncthreads();
    if (tid == NT - 1) *sSum = sumD0;

    // ================= un-rotate into state order =================
    if (tid < NTRANS) {
        int m = NFRAMES % myL;
        for (int o = 0; o < myL; o++) {
            int so = o - m; if (so < 0) so += myL;
            wArr[myBase + o] = vv[myBase + so];
        }
    }
    __syncthreads();

    // ================= argmax (first-index tie-break) =================
    float bv = -3.0e38f;
    int   bi = 0x7FFFFFFF;
    for (int s = tid; s < S; s += NT) {
        float x = wArr[s];
        if (x > bv) { bv = x; bi = s; }
    }
    rv[tid] = bv; ri[tid] = bi;
    __syncthreads();
    for (int off = NT / 2; off > 0; off >>= 1) {
        if (tid < off) {
            float xv = rv[tid + off]; int xi = ri[tid + off];
            if (xv > rv[tid] || (xv == rv[tid] && xi < ri[tid])) { rv[tid] = xv; ri[tid] = xi; }
        }
        __syncthreads();
    }

    // ================= backtrace (segment runs) =================
    if (tid == 0) {
        int s = ri[0];
        if (out_size > NFRAMES) out[NFRAMES] = rv[0] + *sSum;
        out[NFRAMES - 1] = (float)s;
        int t = NFRAMES - 1;
        while (t >= 1) {
            int iv = sIvl[s];
            int o  = s - sBase[iv];
            int steps = (o < t) ? o : t;
            for (int j = 1; j <= steps; j++) out[t - j] = (float)(s - j);
            t -= steps; s -= steps;
            if (t >= 1) {
                int p = g_bp[t * NTRANS + iv];   // s is first state of interval iv
                out[t - 1] = (float)p;
                s = p; t--;
            }
        }
    }
}

extern "C" void kernel_launch(void* const* d_in, const int* in_sizes, int n_in,
                              void* d_out, int out_size) {
    const float* acts         = (const float*)d_in[0];
    const float* log_trans    = (const float*)d_in[1];
    const int*   prev_last    = (const int*)d_in[2];
    const int*   first_states = (const int*)d_in[3];
    const int*   pointer      = (const int*)d_in[4];
    int S = in_sizes[4];

    cudaFuncSetAttribute(viterbi_kernel, cudaFuncAttributeMaxDynamicSharedMemorySize, SMEM_BYTES);

    dens_kernel<<<(NFRAMES + 255) / 256, 256>>>(acts);
    viterbi_kernel<<<1, NT, SMEM_BYTES>>>(log_trans, prev_last, first_states, pointer,
                                          (float*)d_out, S, out_size);
}

// round 6
// speedup vs baseline: 3.3812x; 2.8197x over previous
#include <cuda_runtime.h>
#include <math.h>

#define NT        256
#define NFRAMES   6000
#define NTEMPI    60
#define NBEATS    4
#define NTRANS    240
#define LT_STRIDE 61
#define LT2SZ     (NBEATS * NTEMPI * LT_STRIDE)   // 14640
#define SPAD      15360
#define BFR       24          // frames per block; requires BFR <= minL-1 (minL=28)
#define WREG      44          // fixed register window width (max true window ~38)

// -------- smem layout (floats) --------
#define OFF_VV    0
#define OFF_LT2   (OFF_VV + SPAD)                 // 15360
#define OFF_SC    (OFF_LT2 + LT2SZ)               // 30000
#define OFF_CC    (OFF_SC + BFR * 256)            // 36144 ; 32 float2 = 64 floats
#define OFF_PREV  (OFF_CC + 64)                   // 36208
#define OFF_BASE  (OFF_PREV + NTRANS)
#define OFF_LEN   (OFF_BASE + NTRANS)
#define OFF_LO    (OFF_LEN + NTRANS)
#define OFF_HI    (OFF_LO + NTRANS)
#define OFF_RV    (OFF_HI + NTRANS)               // 256
#define OFF_RI    (OFF_RV + NT)                   // 256
#define OFF_SUM   (OFF_RI + NT)                   // 8
#define OFF_IVL   (OFF_SUM + 8)                   // ushort[SPAD] = SPAD/2 floats
#define SMEM_FLOATS (OFF_IVL + SPAD / 2)
#define SMEM_BYTES  (SMEM_FLOATS * 4)

__device__ float4 g_c4[NFRAMES];                  // {d1-d0, d2-d0, d0, 0}
__device__ float  g_cand[NFRAMES * NTRANS];       // per-frame gathered candidates

__global__ void dens_kernel(const float* __restrict__ acts) {
    int t = blockIdx.x * blockDim.x + threadIdx.x;
    if (t < NFRAMES) {
        float ab = acts[2 * t];
        float ad = acts[2 * t + 1];
        float d0 = logf((1.0f - ab - ad) / 15.0f);
        float d1 = logf(ab);
        float d2 = logf(ad);
        g_c4[t] = make_float4(d1 - d0, d2 - d0, d0, 0.0f);
    }
}

__global__ __launch_bounds__(NT, 1)
void viterbi_kernel(const float* __restrict__ log_trans,
                    const int*   __restrict__ prev_last,
                    const int*   __restrict__ first_states,
                    const int*   __restrict__ pointer,
                    float*       __restrict__ out,
                    int S, int out_size)
{
    extern __shared__ float sm[];
    float*          vv    = sm + OFF_VV;
    float*          lt2   = sm + OFF_LT2;
    float*          sC    = sm + OFF_SC;
    float*          sCC   = sm + OFF_CC;     // float pairs {cAdd1, cAdd2} per block frame
    int*            sPrev = (int*)(sm + OFF_PREV);
    int*            sBase = (int*)(sm + OFF_BASE);
    int*            sLen  = (int*)(sm + OFF_LEN);
    int*            sLo   = (int*)(sm + OFF_LO);
    int*            sHi   = (int*)(sm + OFF_HI);
    float*          rv    = sm + OFF_RV;
    int*            ri    = (int*)(sm + OFF_RI);
    float*          sSum  = sm + OFF_SUM;
    unsigned short* sIvl  = (unsigned short*)(sm + OFF_IVL);

    const int tid = threadIdx.x;
    const int nsb = S / NBEATS;
    const bool active = (tid < NTRANS);

    // ================= init =================
    float v0 = -logf((float)S);
    for (int s = tid; s < SPAD; s += NT) vv[s] = v0;
    for (int idx = tid; idx < NBEATS * NTEMPI * NTEMPI; idx += NT) {
        int b = idx / (NTEMPI * NTEMPI);
        int r = (idx - b * NTEMPI * NTEMPI) / NTEMPI;
        int c = idx % NTEMPI;
        lt2[b * NTEMPI * LT_STRIDE + r * LT_STRIDE + c] = log_trans[idx];
    }
    if (active) {
        sPrev[tid] = prev_last[tid];
        sBase[tid] = first_states[tid];
    }
    // total d0 (for logp)
    {
        float acc = 0.0f;
        for (int t = tid; t < NFRAMES; t += NT) acc += g_c4[t].z;
        rv[tid] = acc;
        __syncthreads();
        for (int off = NT / 2; off > 0; off >>= 1) {
            if (tid < off) rv[tid] += rv[tid + off];
            __syncthreads();
        }
        if (tid == 0) *sSum = rv[0];
    }
    __syncthreads();

    // per-interval statics
    int b60 = 0, i60 = 0, myBase = 0, myL = 1, srcBase = 0, myM = 0, psel = 0, Lo = 0;
    float rr[WREG];
    if (active) {
        b60 = tid / NTEMPI;
        i60 = tid - b60 * NTEMPI;
        myBase = sBase[tid];
        int end = (i60 < NTEMPI - 1) ? sBase[tid + 1] : (b60 + 1) * nsb;
        myL = end - myBase;
        srcBase = (b60 == 0) ? (myBase + 3 * nsb) : (myBase - nsb);
        // fix-state count (contiguous offsets 1..m with pointer != 0)
        for (int o = 1; o < myL && o <= 7; o++) {
            if (pointer[myBase + o] != 0) myM = o; else break;
        }
        psel = (pointer[myBase] == 2) ? 1 : 0;
        // finite-transition window
        const float* row = lt2 + b60 * NTEMPI * LT_STRIDE + i60 * LT_STRIDE;
        int lo = NTEMPI, hi = -1;
        for (int j = 0; j < NTEMPI; j++)
            if (row[j] > -1e29f) { if (j < lo) lo = j; hi = j; }
        sLo[tid] = lo; sHi[tid] = hi;
        Lo = lo; if (Lo > NTEMPI - WREG) Lo = NTEMPI - WREG; if (Lo < 0) Lo = 0;
        #pragma unroll
        for (int jj = 0; jj < WREG; jj++) rr[jj] = row[Lo + jj];
        // initial-value fix corrections: slot o0 (=state o0) for o0 = 0..myM-1
        const float* c4f = (const float*)g_c4;
        float run = 0.0f;
        for (int i = 0; i < myM; i++) {
            run += c4f[4 * i + psel];
            vv[myBase + (myM - 1 - i)] = v0 + run;
        }
        sLen[tid] = myL;
        for (int o = 0; o < myL; o++) sIvl[myBase + o] = (unsigned short)tid;
    }
    __syncthreads();

    int k = myL - 1;    // rotating slot offset of state o=0

    // ================= 250 blocks x 24 frames =================
    for (int t0 = 0; t0 < NFRAMES; t0 += BFR) {
        // ---- gather phase: read last-state slots (written >= 27 frames ago) ----
        if (active) {
            int kg = k;
            #pragma unroll 1
            for (int q = 0; q < BFR; q++) {
                float val = vv[srcBase + kg];
                sC[q * 256 + tid] = val;
                g_cand[(t0 + q) * NTRANS + tid] = val;
                kg = (kg == 0) ? (myL - 1) : (kg - 1);
            }
        }
        if (tid < BFR + 8) {   // per-frame dens deltas for this block (+6 lookahead)
            int fr = t0 + tid; if (fr > NFRAMES - 1) fr = NFRAMES - 1;
            float4 c = g_c4[fr];
            sCC[2 * tid]     = c.x;
            sCC[2 * tid + 1] = c.y;
        }
        __syncthreads();

        // ---- compute phase ----
        if (active) {
            const float* ccp = sCC + psel;
            #pragma unroll 1
            for (int q = 0; q < BFR; q++) {
                int t = t0 + q;
                const float* c = sC + q * 256 + b60 * NTEMPI + Lo;
                float m0 = -3.0e38f, m1 = -3.0e38f, m2 = -3.0e38f, m3 = -3.0e38f;
                #pragma unroll
                for (int jj = 0; jj < WREG; jj += 4) {
                    m0 = fmaxf(m0, c[jj]     + rr[jj]);
                    m1 = fmaxf(m1, c[jj + 1] + rr[jj + 1]);
                    m2 = fmaxf(m2, c[jj + 2] + rr[jj + 2]);
                    m3 = fmaxf(m3, c[jj + 3] + rr[jj + 3]);
                }
                float val = fmaxf(fmaxf(m0, m1), fmaxf(m2, m3));
                // own-frame dens + folded future fix adds (same FADD order as reference)
                val += ccp[2 * q];
                #pragma unroll 1
                for (int i = 1; i <= myM; i++) {
                    if (t + i <= NFRAMES - 1) val += ccp[2 * (q + i)];
                }
                vv[myBase + k] = val;
                k = (k == 0) ? (myL - 1) : (k - 1);
            }
        }
        __syncthreads();
    }

    // ================= argmax over final v (first-index tie-break) =================
    // per-interval scan in state order (slot = (o - NFRAMES%L) mod L), then block reduce
    float bv = -3.0e38f;
    int   bi = 0x7FFFFFFF;
    if (active) {
        int r = NFRAMES % myL;
        for (int o = 0; o < myL; o++) {
            int so = o - r; if (so < 0) so += myL;
            float x = vv[myBase + so];
            if (x > bv) { bv = x; bi = myBase + o; }
        }
    }
    rv[tid] = bv; ri[tid] = bi;
    __syncthreads();
    for (int off = NT / 2; off > 0; off >>= 1) {
        if (tid < off) {
            float xv = rv[tid + off]; int xi = ri[tid + off];
            if (xv > rv[tid] || (xv == rv[tid] && xi < ri[tid])) { rv[tid] = xv; ri[tid] = xi; }
        }
        __syncthreads();
    }

    // ================= backtrace (thread 0), argmax recomputed at crossings =====
    if (tid == 0) {
        int s = ri[0];
        if (out_size > NFRAMES) out[NFRAMES] = rv[0] + *sSum;
        out[NFRAMES - 1] = (float)s;
        int t = NFRAMES - 1;
        while (t >= 1) {
            int iv = sIvl[s];
            int o  = s - sBase[iv];
            int steps = (o < t) ? o : t;
            for (int j = 1; j <= steps; j++) out[t - j] = (float)(s - j);
            t -= steps; s -= steps;
            if (t >= 1) {
                // s is the first state of interval iv; recompute frame-t argmax
                int b = iv / NTEMPI, i = iv - b * NTEMPI;
                const float* row  = lt2 + b * NTEMPI * LT_STRIDE + i * LT_STRIDE;
                const float* cand = g_cand + t * NTRANS + b * NTEMPI;
                int lo = sLo[iv], hi = sHi[iv];
                float best = -3.0e38f; int arg = lo;
                for (int j = lo; j <= hi; j++) {
                    float sc = cand[j] + row[j];
                    if (sc > best) { best = sc; arg = j; }
                }
                int p = sPrev[b * NTEMPI + arg];
                out[t - 1] = (float)p;
                s = p; t--;
            }
        }
    }
}

extern "C" void kernel_launch(void* const* d_in, const int* in_sizes, int n_in,
                              void* d_out, int out_size) {
    const float* acts         = (const float*)d_in[0];
    const float* log_trans    = (const float*)d_in[1];
    const int*   prev_last    = (const int*)d_in[2];
    const int*   first_states = (const int*)d_in[3];
    const int*   pointer      = (const int*)d_in[4];
    int S = in_sizes[4];

    cudaFuncSetAttribute(viterbi_kernel, cudaFuncAttributeMaxDynamicSharedMemorySize, SMEM_BYTES);

    dens_kernel<<<(NFRAMES + 255) / 256, 256>>>(acts);
    viterbi_kernel<<<1, NT, SMEM_BYTES>>>(log_trans, prev_last, first_states, pointer,
                                          (float*)d_out, S, out_size);
}